// round 2
// baseline (speedup 1.0000x reference)
#include <cuda_runtime.h>
#include <cuda_bf16.h>
#include <math.h>

// Problem dims
#define B_ 32
#define T_ 64
#define P_ 10
#define I_ 1024
#define H_ 1024
#define C_ 8
#define G4 4096           // 4*H
#define M_ (B_*T_*P_)     // 20480 rows of x viewed as (M, I)

// Scratch (device globals; no allocation allowed)
__device__ float d_xwx[(size_t)T_*B_*P_*H_];   // 80 MB: x@Wx^T, layout [t][b][p][h]
__device__ float d_apart[8*B_*H_];             // split-K partials of h@Wh^T
__device__ float d_gpart[4*B_*G4];             // split-K partials of gates GEMM
__device__ float d_ucat[B_*2048];              // [b][0:1024]=emb, [b][1024:2048]=h
__device__ float d_c[B_*H_];                   // cell state

__device__ __forceinline__ float tanh_fast(float x) {
    float y; asm("tanh.approx.f32 %0, %1;" : "=f"(y) : "f"(x)); return y;
}
__device__ __forceinline__ float sigmoidf(float x) {
    return 1.0f / (1.0f + expf(-x));
}

// ---------------------------------------------------------------------------
// Kernel 0: zero initial state
// ---------------------------------------------------------------------------
__global__ void zero_state() {
    int i0 = blockIdx.x * 256 + threadIdx.x;
    for (int i = i0; i < B_*2048; i += 96*256) d_ucat[i] = 0.0f;
    for (int i = i0; i < B_*H_;   i += 96*256) d_c[i]    = 0.0f;
}

// ---------------------------------------------------------------------------
// Kernel 1: xwx[t,b,p,h] = sum_i x[b,t,p,i]*Wx[h,i]
// C[M,N] = A(M,K) * B(N,K)^T,  M=20480, N=1024, K=1024
// 128x128 tile, BK=8, 256 threads, 8x8 microtile.
// ---------------------------------------------------------------------------
__global__ __launch_bounds__(256, 2) void sgemm_xwx(
    const float* __restrict__ A, const float* __restrict__ Bm)
{
    __shared__ float As[8][128];
    __shared__ float Bs[8][128];
    const int tid = threadIdx.x;
    const int m0 = blockIdx.y * 128;
    const int n0 = blockIdx.x * 128;
    const int tx = tid & 15;
    const int ty = tid >> 4;

    float acc[8][8];
#pragma unroll
    for (int i = 0; i < 8; i++)
#pragma unroll
        for (int j = 0; j < 8; j++) acc[i][j] = 0.0f;

    const int ar = tid >> 1;          // 0..127
    const int ac = (tid & 1) * 4;     // 0 or 4
    const float* Aptr = A  + (size_t)(m0 + ar) * I_ + ac;
    const float* Bptr = Bm + (size_t)(n0 + ar) * I_ + ac;

    for (int kb = 0; kb < I_; kb += 8) {
        float4 av = *(const float4*)(Aptr + kb);
        float4 bv = *(const float4*)(Bptr + kb);
        As[ac+0][ar] = av.x; As[ac+1][ar] = av.y; As[ac+2][ar] = av.z; As[ac+3][ar] = av.w;
        Bs[ac+0][ar] = bv.x; Bs[ac+1][ar] = bv.y; Bs[ac+2][ar] = bv.z; Bs[ac+3][ar] = bv.w;
        __syncthreads();
#pragma unroll
        for (int kk = 0; kk < 8; kk++) {
            float a_f[8], b_f[8];
            *(float4*)(a_f)     = *(const float4*)&As[kk][ty*8];
            *(float4*)(a_f + 4) = *(const float4*)&As[kk][ty*8 + 4];
            *(float4*)(b_f)     = *(const float4*)&Bs[kk][tx*8];
            *(float4*)(b_f + 4) = *(const float4*)&Bs[kk][tx*8 + 4];
#pragma unroll
            for (int i = 0; i < 8; i++)
#pragma unroll
                for (int j = 0; j < 8; j++)
                    acc[i][j] += a_f[i] * b_f[j];
        }
        __syncthreads();
    }

    // permuted write: row r=(b*T+t)*P+p  ->  out row ((t*B+b)*P+p)
#pragma unroll
    for (int i = 0; i < 8; i++) {
        int r   = m0 + ty*8 + i;
        int b   = r / (T_*P_);
        int rem = r % (T_*P_);
        int t   = rem / P_;
        int p   = rem % P_;
        float* o = d_xwx + (size_t)((t*B_ + b)*P_ + p) * H_ + n0 + tx*8;
        *(float4*)(o)     = *(float4*)&acc[i][0];
        *(float4*)(o + 4) = *(float4*)&acc[i][4];
    }
}

// ---------------------------------------------------------------------------
// Skinny GEMM body: part[ks][b][n] = sum_{i in chunk} U[b][i] * W(n,i)
// U: [32 x Ktot] rows with stride ldu. W rows have length 1024; segment
// selected per 64-chunk (i < K0 -> W0, else W1 at i-K0).
// Block: 64 n-values, all 32 b. 256 threads, microtile 2b x 4n.
// ---------------------------------------------------------------------------
template<int CHUNK>
__device__ __forceinline__ void skinny_body(
    const float* __restrict__ U, int ldu,
    const float* __restrict__ W0, const float* __restrict__ W1,
    int K0, int N, float* __restrict__ part)
{
    __shared__ float u_s[64][32];   // [i][b]
    __shared__ float w_s[64][64];   // [i][n_local]
    const int tid = threadIdx.x;
    const int n0 = blockIdx.x * 64;
    const int i_start = blockIdx.y * CHUNK;
    const int tn = tid & 15;        // 0..15 -> 4 n each
    const int tb = tid >> 4;        // 0..15 -> 2 b each

    float acc[2][4] = {{0,0,0,0},{0,0,0,0}};

    for (int cb = 0; cb < CHUNK; cb += 64) {
        const int ib = i_start + cb;
        const float* W = (ib < K0) ? (W0 + ib) : (W1 + (ib - K0));

        // u tile: conflict-free STS (lanes -> distinct b banks), L1-reused LDG
        for (int l = tid; l < 64*32; l += 256) {
            int i = l >> 5, b = l & 31;
            u_s[i][b] = U[b*ldu + ib + i];
        }
        // w tile: lanes -> distinct n (conflict-free STS), float4 over i
        for (int l = tid; l < 1024; l += 256) {
            int n  = l & 63;
            int i4 = (l >> 6) << 2;
            float4 wv = *(const float4*)(W + (size_t)(n0 + n) * 1024 + i4);
            w_s[i4+0][n] = wv.x; w_s[i4+1][n] = wv.y;
            w_s[i4+2][n] = wv.z; w_s[i4+3][n] = wv.w;
        }
        __syncthreads();
#pragma unroll
        for (int i = 0; i < 64; i++) {
            float2 uu = *(const float2*)&u_s[i][tb*2];
            float4 ww = *(const float4*)&w_s[i][tn*4];
            acc[0][0] += uu.x*ww.x; acc[0][1] += uu.x*ww.y;
            acc[0][2] += uu.x*ww.z; acc[0][3] += uu.x*ww.w;
            acc[1][0] += uu.y*ww.x; acc[1][1] += uu.y*ww.y;
            acc[1][2] += uu.y*ww.z; acc[1][3] += uu.y*ww.w;
        }
        __syncthreads();
    }

    const int ks = blockIdx.y;
#pragma unroll
    for (int bb = 0; bb < 2; bb++) {
        int b = tb*2 + bb;
#pragma unroll
        for (int nn = 0; nn < 4; nn++)
            part[(ks*B_ + b)*N + n0 + tn*4 + nn] = acc[bb][nn];
    }
}

// a_part = h @ Wh^T  (grid 16 x 8, chunk 128)
__global__ __launch_bounds__(256) void ka_kernel(const float* __restrict__ Wh) {
    skinny_body<128>(&d_ucat[1024], 2048, Wh, Wh, 1024, H_, d_apart);
}
// g_part = [emb||h] @ [Wih||Whh]^T  (grid 64 x 4, chunk 512)
__global__ __launch_bounds__(256) void kg_kernel(const float* __restrict__ Wih,
                                                 const float* __restrict__ Whh) {
    skinny_body<512>(d_ucat, 2048, Wih, Whh, 1024, G4, d_gpart);
}

// ---------------------------------------------------------------------------
// Attention: scores -> softmax over P -> emb (writes d_ucat[b][0:1024])
// ---------------------------------------------------------------------------
__global__ __launch_bounds__(256) void kattn(
    int t, const float* __restrict__ b_att, const float* __restrict__ v,
    const float* __restrict__ x)
{
    const int b = blockIdx.x, tid = threadIdx.x;
    float sp[P_];
#pragma unroll
    for (int p = 0; p < P_; p++) sp[p] = 0.0f;

    for (int hb = 0; hb < H_; hb += 256) {
        int h = hb + tid;
        float ah = b_att[h];
#pragma unroll
        for (int ks = 0; ks < 8; ks++) ah += d_apart[(ks*B_ + b)*H_ + h];
        float vh = v[h];
        const float* xw = &d_xwx[(size_t)((t*B_ + b)*P_) * H_ + h];
#pragma unroll
        for (int p = 0; p < P_; p++)
            sp[p] += tanh_fast(xw[p*H_] + ah) * vh;
    }

    __shared__ float red[P_][8];
#pragma unroll
    for (int p = 0; p < P_; p++) {
        float s = sp[p];
#pragma unroll
        for (int o = 16; o; o >>= 1) s += __shfl_xor_sync(0xffffffffu, s, o);
        sp[p] = s;
    }
    int warp = tid >> 5, lane = tid & 31;
    if (lane == 0) {
#pragma unroll
        for (int p = 0; p < P_; p++) red[p][warp] = sp[p];
    }
    __syncthreads();
    __shared__ float sc[P_];
    if (tid < P_) {
        float s = 0.0f;
#pragma unroll
        for (int w = 0; w < 8; w++) s += red[tid][w];
        sc[tid] = s;
    }
    __syncthreads();

    float mx = -1e30f;
#pragma unroll
    for (int p = 0; p < P_; p++) mx = fmaxf(mx, sc[p]);
    float al[P_], ssum = 0.0f;
#pragma unroll
    for (int p = 0; p < P_; p++) { al[p] = expf(sc[p] - mx); ssum += al[p]; }
    float inv = 1.0f / ssum;

    const float* xb = &x[(size_t)((b*T_ + t)*P_) * I_];
    for (int i = tid; i < I_; i += 256) {
        float e = 0.0f;
#pragma unroll
        for (int p = 0; p < P_; p++) e += al[p] * xb[p*I_ + i];
        d_ucat[b*2048 + i] = e * inv;
    }
}

// ---------------------------------------------------------------------------
// Cell update: gates from g_part, new c and h
// ---------------------------------------------------------------------------
__global__ __launch_bounds__(256) void kcell(const float* __restrict__ bih,
                                             const float* __restrict__ bhh)
{
    int idx = blockIdx.x * 256 + threadIdx.x;   // 32768
    int b = idx >> 10, j = idx & 1023;
    float g4[4];
#pragma unroll
    for (int g = 0; g < 4; g++) {
        int n = g*H_ + j;
        float s = bih[n] + bhh[n];
#pragma unroll
        for (int ks = 0; ks < 4; ks++) s += d_gpart[(ks*B_ + b)*G4 + n];
        g4[g] = s;
    }
    float ig = sigmoidf(g4[0]);
    float fg = sigmoidf(g4[1]);
    float gg = tanhf(g4[2]);
    float og = sigmoidf(g4[3]);
    float cn = fg * d_c[idx] + ig * gg;
    d_c[idx] = cn;
    d_ucat[b*2048 + 1024 + j] = og * tanhf(cn);
}

// ---------------------------------------------------------------------------
// Final FC: out[b][c] = h[b] . Wfc[c] + bfc[c]   (one warp per output)
// ---------------------------------------------------------------------------
__global__ __launch_bounds__(256) void kfc(const float* __restrict__ Wfc,
                                           const float* __restrict__ bfc,
                                           float* __restrict__ out)
{
    int b = blockIdx.x;
    int w = threadIdx.x >> 5;   // class
    int lane = threadIdx.x & 31;
    const float* h = &d_ucat[b*2048 + 1024];
    float acc = 0.0f;
    for (int i = lane; i < H_; i += 32) acc += h[i] * Wfc[w*H_ + i];
#pragma unroll
    for (int o = 16; o; o >>= 1) acc += __shfl_xor_sync(0xffffffffu, acc, o);
    if (lane == 0) out[b*C_ + w] = acc + bfc[w];
}

// ---------------------------------------------------------------------------
extern "C" void kernel_launch(void* const* d_in, const int* in_sizes, int n_in,
                              void* d_out, int out_size)
{
    const float* x    = (const float*)d_in[0];
    const float* Wx   = (const float*)d_in[1];
    const float* Wh   = (const float*)d_in[2];
    const float* batt = (const float*)d_in[3];
    const float* v    = (const float*)d_in[4];
    const float* Wih  = (const float*)d_in[5];
    const float* Whh  = (const float*)d_in[6];
    const float* bih  = (const float*)d_in[7];
    const float* bhh  = (const float*)d_in[8];
    const float* Wfc  = (const float*)d_in[9];
    const float* bfc  = (const float*)d_in[10];
    float* out = (float*)d_out;

    zero_state<<<96, 256>>>();
    sgemm_xwx<<<dim3(H_/128, M_/128), 256>>>(x, Wx);

    for (int t = 0; t < T_; t++) {
        ka_kernel<<<dim3(16, 8), 256>>>(Wh);
        kattn<<<B_, 256>>>(t, batt, v, x);
        kg_kernel<<<dim3(64, 4), 256>>>(Wih, Whh);
        kcell<<<128, 256>>>(bih, bhh);
    }
    kfc<<<B_, 256>>>(Wfc, bfc, out);
}